// round 17
// baseline (speedup 1.0000x reference)
#include <cuda_runtime.h>
#include <cuda_fp16.h>

// PassiveWaveDigitalMixer — fused 9-point periodic stencil + gated flows.
// B=4, C=128, H=W=256, O=16, M=32 (fixed shapes).
// R15: software-pipelined 2-row variant. Each warp covers a full W row pair;
// iteration k computes channel c=ty+8k while iteration k+1's 8 row-vector
// loads are ALREADY in flight (register double-buffer: 2 x 8 float4 stages).
// Memory requests never idle while computing -> DRAM duty cycle up.
// Steer mults register-held as half2 (R5/R11 lesson), packed-half2 gating,
// fp32 flows, __stcs stores.

constexpr int B = 4, C = 128, H = 256, W = 256, O = 16, M = 32;
constexpr int HW = H * W;
constexpr float GAIN_CAP = 0.99f;
constexpr float EPS = 1e-4f;

__device__ __forceinline__ float softplus_eps(float p) {
    return fmaxf(p, 0.0f) + log1pf(expf(-fabsf(p))) + EPS;
}

__device__ __forceinline__ float4 add4(float4 a, float4 b) {
    return make_float4(a.x + b.x, a.y + b.y, a.z + b.z, a.w + b.w);
}

struct V8 { float4 m0, m1, a0, a1, b0, b1, q0, q1; };

__global__ __launch_bounds__(256, 2)
void pwdm_kernel(const float* __restrict__ x,
                 const float* __restrict__ steer,
                 const float* __restrict__ modulation,
                 const float* __restrict__ r_center,
                 const float* __restrict__ r_horizontal,
                 const float* __restrict__ r_vertical,
                 const float* __restrict__ r_diag,
                 const float* __restrict__ gain_h,
                 const float* __restrict__ gain_v,
                 const float* __restrict__ gain_d,
                 const float* __restrict__ steer_w,
                 const float* __restrict__ mod_w,
                 float* __restrict__ out)
{
    __shared__ float s_invh[C], s_invv[C], s_invd[C];
    __shared__ float s_gh[C],   s_gv[C],   s_gd[C];
    __shared__ __half s_t[2][3][W];   // pre-expanded (1 + 0.2*tanh(field))

    const int tx  = threadIdx.x;          // 0..31 lane (8 w-elems each)
    const int ty  = threadIdx.y;          // 0..7  channel sub-lane
    const int tid = ty * 32 + tx;
    const int h0  = blockIdx.x * 2;       // first of the row pair
    const int b   = blockIdx.y;

    // --- modulation deltas (broadcast loads, every thread) ---
    float d0 = 0.f, d1 = 0.f, d2 = 0.f;
    #pragma unroll
    for (int m = 0; m < M; m++) {
        float mv = modulation[b * M + m];
        d0 = fmaf(mv, mod_w[0 * M + m], d0);
        d1 = fmaf(mv, mod_w[1 * M + m], d1);
        d2 = fmaf(mv, mod_w[2 * M + m], d2);
    }
    d0 = tanhf(d0); d1 = tanhf(d1); d2 = tanhf(d2);

    // --- per-channel constants ---
    if (tid < C) {
        float spc = softplus_eps(r_center[tid]);
        s_invh[tid] = 1.0f / (spc + softplus_eps(r_horizontal[tid]));
        s_invv[tid] = 1.0f / (spc + softplus_eps(r_vertical[tid]));
        s_invd[tid] = 1.0f / (2.0f * (spc + softplus_eps(r_diag[tid])));
        s_gh[tid] = tanhf(gain_h[tid]) * (1.0f + 0.1f * d0);
        s_gv[tid] = tanhf(gain_v[tid]) * (1.0f + 0.1f * d1);
        s_gd[tid] = tanhf(gain_d[tid]) * (1.0f + 0.1f * d2);
    }

    // --- steer-field multipliers (2 rows), vectorized:
    //     thread covers row (tid>>7) and 4 w positions ((tid&127)*2)... use
    //     128 threads per row: wq = (tid & 127) * 2 -> float2 loads. Simpler:
    //     row = tid >> 7 (0..1), wq = (tid & 127) * 2 (two scalars). To keep
    //     float4 loads: 64 threads per row cover 4 w each; 2 rows use 128
    //     threads; remaining 128 threads idle here (cheap prologue).
    if (tid < 128) {
        const int r  = tid >> 6;          // 0..1
        const int wq = (tid & 63) * 4;    // w base
        float4 a0 = make_float4(0.f, 0.f, 0.f, 0.f);
        float4 a1 = a0, a2 = a0;
        const float4* sp = reinterpret_cast<const float4*>(
            steer + ((size_t)b * O * H + (h0 + r)) * W + wq);
        const int planeF4 = HW / 4;
        #pragma unroll
        for (int o = 0; o < O; o++) {
            float4 sv = sp[(size_t)o * planeF4];
            float w0c = steer_w[0 * O + o];
            float w1c = steer_w[1 * O + o];
            float w2c = steer_w[2 * O + o];
            a0.x = fmaf(sv.x, w0c, a0.x); a0.y = fmaf(sv.y, w0c, a0.y);
            a0.z = fmaf(sv.z, w0c, a0.z); a0.w = fmaf(sv.w, w0c, a0.w);
            a1.x = fmaf(sv.x, w1c, a1.x); a1.y = fmaf(sv.y, w1c, a1.y);
            a1.z = fmaf(sv.z, w1c, a1.z); a1.w = fmaf(sv.w, w1c, a1.w);
            a2.x = fmaf(sv.x, w2c, a2.x); a2.y = fmaf(sv.y, w2c, a2.y);
            a2.z = fmaf(sv.z, w2c, a2.z); a2.w = fmaf(sv.w, w2c, a2.w);
        }
        #pragma unroll
        for (int d = 0; d < 3; d++) {
            float4 a = (d == 0) ? a0 : (d == 1) ? a1 : a2;
            __half2 lo = __floats2half2_rn(fmaf(0.2f, tanhf(a.x), 1.0f),
                                           fmaf(0.2f, tanhf(a.y), 1.0f));
            __half2 hi = __floats2half2_rn(fmaf(0.2f, tanhf(a.z), 1.0f),
                                           fmaf(0.2f, tanhf(a.w), 1.0f));
            *reinterpret_cast<__half2*>(&s_t[r][d][wq])     = lo;
            *reinterpret_cast<__half2*>(&s_t[r][d][wq + 2]) = hi;
        }
    }
    __syncthreads();

    // --- hoist this lane's multipliers: 2 rows x 3 dirs x 4 half2 regs ---
    const int w0 = tx * 8;
    __half2 st[2][3][4];
    #pragma unroll
    for (int r = 0; r < 2; r++)
        #pragma unroll
        for (int dir = 0; dir < 3; dir++)
            #pragma unroll
            for (int j = 0; j < 4; j++)
                st[r][dir][j] =
                    *reinterpret_cast<const __half2*>(&s_t[r][dir][w0 + 2 * j]);

    const int hm = (h0 - 1) & (H - 1);
    const int hp = (h0 + 2) & (H - 1);
    const size_t base = (size_t)b * C * HW + (size_t)ty * HW + w0;
    const float* pm = x + base + (size_t)hm * W;
    const float* p0 = x + base + (size_t)h0 * W;
    const float* pp = x + base + (size_t)hp * W;
    float*       o0 = out + base + (size_t)h0 * W;
    const size_t cstep = (size_t)8 * HW;

    const unsigned FULL = 0xffffffffu;
    const int laneL = (tx + 31) & 31;
    const int laneR = (tx + 1) & 31;
    const __half2 zero2 = __float2half2_rn(0.0f);
    const __half2 cap2  = __float2half2_rn(GAIN_CAP);

    auto loadV = [&](size_t off) {
        V8 v;
        v.m0 = *reinterpret_cast<const float4*>(pm + off);
        v.m1 = *reinterpret_cast<const float4*>(pm + off + 4);
        v.a0 = *reinterpret_cast<const float4*>(p0 + off);
        v.a1 = *reinterpret_cast<const float4*>(p0 + off + 4);
        v.b0 = *reinterpret_cast<const float4*>(p0 + W + off);
        v.b1 = *reinterpret_cast<const float4*>(p0 + W + off + 4);
        v.q0 = *reinterpret_cast<const float4*>(pp + off);
        v.q1 = *reinterpret_cast<const float4*>(pp + off + 4);
        return v;
    };

    float invh, invv, invd;
    __half2 gh2, gv2, gd2;

    // one output row: centers (cA,cB), vertical sums (sA,sB), mults stR
    auto do_row = [&](float4 cA_, float4 cB_, float4 sA_, float4 sB_,
                      __half2 (&stR)[3][4], float* op) {
        float ce[10], se[10];
        ce[1] = cA_.x; ce[2] = cA_.y; ce[3] = cA_.z; ce[4] = cA_.w;
        ce[5] = cB_.x; ce[6] = cB_.y; ce[7] = cB_.z; ce[8] = cB_.w;
        se[1] = sA_.x; se[2] = sA_.y; se[3] = sA_.z; se[4] = sA_.w;
        se[5] = sB_.x; se[6] = sB_.y; se[7] = sB_.z; se[8] = sB_.w;
        ce[0] = __shfl_sync(FULL, ce[8], laneL);
        ce[9] = __shfl_sync(FULL, ce[1], laneR);
        se[0] = __shfl_sync(FULL, se[8], laneL);
        se[9] = __shfl_sync(FULL, se[1], laneR);

        float r8[8];
        #pragma unroll
        for (int j = 0; j < 4; j++) {
            __half2 gH = __hmin2(__hmax2(__hmul2(gh2, stR[0][j]), zero2), cap2);
            __half2 gV = __hmin2(__hmax2(__hmul2(gv2, stR[1][j]), zero2), cap2);
            __half2 gD = __hmin2(__hmax2(__hmul2(gd2, stR[2][j]), zero2), cap2);
            float2 ghf = __half22float2(gH);
            float2 gvf = __half22float2(gV);
            float2 gdf = __half22float2(gD);
            #pragma unroll
            for (int k = 0; k < 2; k++) {
                const int i = 2 * j + k;
                float cv = ce[i + 1];
                float fh = (ce[i] + ce[i + 2] - 2.0f * cv) * invh;
                float fv = (se[i + 1]          - 2.0f * cv) * invv;
                float fd = (se[i] + se[i + 2]  - 4.0f * cv) * invd;
                float gh = k ? ghf.y : ghf.x;
                float gv = k ? gvf.y : gvf.x;
                float gd = k ? gdf.y : gdf.x;
                r8[i] = fmaf(gh, fh, fmaf(gv, fv, fmaf(gd, fd, cv)));
            }
        }
        __stcs(reinterpret_cast<float4*>(op),
               make_float4(r8[0], r8[1], r8[2], r8[3]));
        __stcs(reinterpret_cast<float4*>(op + 4),
               make_float4(r8[4], r8[5], r8[6], r8[7]));
    };

    // ---- software pipeline: prefetch k+1 while computing k ----
    constexpr int NIT = C / 8;   // 16 channel iterations
    V8 cur = loadV(0);
    float* oc = o0;

    #pragma unroll 4
    for (int k = 0; k < NIT; k++) {
        V8 nxt;
        if (k + 1 < NIT)
            nxt = loadV((size_t)(k + 1) * cstep);   // in flight during compute

        const int c = ty + k * 8;
        invh = s_invh[c]; invv = s_invv[c]; invd = s_invd[c];
        gh2 = __float2half2_rn(s_gh[c]);
        gv2 = __float2half2_rn(s_gv[c]);
        gd2 = __float2half2_rn(s_gd[c]);

        // row h0: vsum = m + b
        do_row(cur.a0, cur.a1, add4(cur.m0, cur.b0), add4(cur.m1, cur.b1),
               st[0], oc);
        // row h1: vsum = a + q
        do_row(cur.b0, cur.b1, add4(cur.a0, cur.q0), add4(cur.a1, cur.q1),
               st[1], oc + W);

        oc += cstep;
        cur = nxt;
    }
}

extern "C" void kernel_launch(void* const* d_in, const int* in_sizes, int n_in,
                              void* d_out, int out_size)
{
    const float* x            = (const float*)d_in[0];
    const float* steer        = (const float*)d_in[1];
    const float* modulation   = (const float*)d_in[2];
    const float* r_center     = (const float*)d_in[3];
    const float* r_horizontal = (const float*)d_in[4];
    const float* r_vertical   = (const float*)d_in[5];
    const float* r_diag       = (const float*)d_in[6];
    const float* gain_h       = (const float*)d_in[7];
    const float* gain_v       = (const float*)d_in[8];
    const float* gain_d       = (const float*)d_in[9];
    const float* steer_w      = (const float*)d_in[10];
    const float* mod_w        = (const float*)d_in[11];
    float* out = (float*)d_out;

    dim3 block(32, 8, 1);       // one warp per full W row-pair, 8 channel lanes
    dim3 grid(H / 2, B, 1);     // one block per (row pair, b) = 512 blocks
    pwdm_kernel<<<grid, block>>>(x, steer, modulation,
                                 r_center, r_horizontal, r_vertical, r_diag,
                                 gain_h, gain_v, gain_d,
                                 steer_w, mod_w, out);
}